// round 16
// baseline (speedup 1.0000x reference)
#include <cuda_runtime.h>
#include <cuda_fp16.h>

static constexpr long kQSize = 256L * 128 * 512;        // 16,777,216
static constexpr long kAttn  = 8L * 256 * 128 * 256;    // 67,108,864

__device__ __half g_lnL[kQSize];       // LN(left)  fp16
__device__ __half g_lnR[kQSize];       // LN(right) fp16
__device__ __half g_q[kQSize];         // [w][n][c] *0.125, fp16
__device__ __half g_kv[2 * kQSize];    // [w][n][k|v] fp16
__device__ __half g_posp[511 * 1024];  // [p][q_r*0.125 | k_r] fp16
__device__ __half g_vo[kQSize];        // [w][n][c] fp16
__device__ float  g_A12[kAttn];        // logits fp32 (NEVER fp16)
__device__ float  g_T3[kAttn];         // logits fp32, layout [e][w][v][n]
__device__ __half g_P[kAttn];          // probs fp16  [e][w][n][v]
__device__ __half g_wih[1536 * 512];   // in_proj_w fp16
__device__ __half g_woh[512 * 512];    // out_w fp16
__device__ __half g_posh[511 * 512];   // pos fp16

__device__ __forceinline__ float4 ld4(const float* p) {
  return *reinterpret_cast<const float4*>(p);
}
__device__ __forceinline__ void mma16(float (&d)[4], const unsigned (&a)[4],
                                      const unsigned (&b)[2]) {
  asm("mma.sync.aligned.m16n8k16.row.col.f32.f16.f16.f32 "
      "{%0,%1,%2,%3}, {%4,%5,%6,%7}, {%8,%9}, {%0,%1,%2,%3};"
      : "+f"(d[0]), "+f"(d[1]), "+f"(d[2]), "+f"(d[3])
      : "r"(a[0]), "r"(a[1]), "r"(a[2]), "r"(a[3]), "r"(b[0]), "r"(b[1]));
}
__device__ __forceinline__ unsigned s2u(const void* p) {
  return (unsigned)__cvta_generic_to_shared(p);
}
__device__ __forceinline__ void ldsm4(unsigned& r0, unsigned& r1, unsigned& r2,
                                      unsigned& r3, unsigned addr) {
  asm volatile("ldmatrix.sync.aligned.m8n8.x4.shared.b16 {%0,%1,%2,%3}, [%4];"
               : "=r"(r0), "=r"(r1), "=r"(r2), "=r"(r3) : "r"(addr));
}
__device__ __forceinline__ void ldsm4t(unsigned& r0, unsigned& r1, unsigned& r2,
                                       unsigned& r3, unsigned addr) {
  asm volatile("ldmatrix.sync.aligned.m8n8.x4.trans.shared.b16 {%0,%1,%2,%3}, [%4];"
               : "=r"(r0), "=r"(r1), "=r"(r2), "=r"(r3) : "r"(addr));
}
__device__ __forceinline__ void cpa16(void* smem_dst, const void* g, bool pred) {
  unsigned d = s2u(smem_dst);
  int sz = pred ? 16 : 0;
  asm volatile("cp.async.cg.shared.global [%0], [%1], 16, %2;"
               :: "r"(d), "l"(g), "r"(sz));
}
__device__ __forceinline__ void cpa_commit() {
  asm volatile("cp.async.commit_group;" ::: "memory");
}
__device__ __forceinline__ void cpa_wait1() {
  asm volatile("cp.async.wait_group 1;" ::: "memory");
}
__device__ __forceinline__ void st_h4(__half* p, float4 v) {
  __half2 h01 = __floats2half2_rn(v.x, v.y);
  __half2 h23 = __floats2half2_rn(v.z, v.w);
  uint2 u;
  u.x = *reinterpret_cast<unsigned*>(&h01);
  u.y = *reinterpret_cast<unsigned*>(&h23);
  *reinterpret_cast<uint2*>(p) = u;
}

// ------- Convert weights + pos to fp16 (once per launch) -------
__global__ void __launch_bounds__(256) cvt_kernel(const float* __restrict__ w_in,
                                                  const float* __restrict__ w_out,
                                                  const float* __restrict__ pos) {
  int i = blockIdx.x * 256 + threadIdx.x;  // float4 index
  if (i < 196608) {
    st_h4(g_wih + i * 4, ld4(w_in + (long)i * 4));
  } else if (i < 262144) {
    int j = i - 196608;
    st_h4(g_woh + j * 4, ld4(w_out + (long)j * 4));
  } else if (i < 327552) {
    int k = i - 262144;
    st_h4(g_posh + k * 4, ld4(pos + (long)k * 4));
  }
}

// ---------------- LayerNorm: one block per 512-float row, fp16 out ----------------
__global__ void __launch_bounds__(128) ln_kernel(const float* __restrict__ fl,
                                                 const float* __restrict__ fr,
                                                 const float* __restrict__ lw,
                                                 const float* __restrict__ lb) {
  long row = blockIdx.x;
  const float* src;
  __half* dst;
  if (row < 32768) { src = fl + row * 512;           dst = g_lnL + row * 512; }
  else             { src = fr + (row - 32768) * 512; dst = g_lnR + (row - 32768) * 512; }
  int t = threadIdx.x;
  float4 x = ld4(src + t * 4);
  float s  = x.x + x.y + x.z + x.w;
  float q2 = x.x * x.x + x.y * x.y + x.z * x.z + x.w * x.w;
#pragma unroll
  for (int o = 16; o > 0; o >>= 1) {
    s  += __shfl_xor_sync(0xffffffffu, s, o);
    q2 += __shfl_xor_sync(0xffffffffu, q2, o);
  }
  __shared__ float ss[4], sq[4];
  if ((t & 31) == 0) { ss[t >> 5] = s; sq[t >> 5] = q2; }
  __syncthreads();
  s  = ss[0] + ss[1] + ss[2] + ss[3];
  q2 = sq[0] + sq[1] + sq[2] + sq[3];
  float mean = s * (1.f / 512.f);
  float var  = q2 * (1.f / 512.f) - mean * mean;
  float rstd = rsqrtf(var + 1e-5f);
  float4 wv = ld4(lw + t * 4), bv = ld4(lb + t * 4);
  float4 o;
  o.x = (x.x - mean) * rstd * wv.x + bv.x;
  o.y = (x.y - mean) * rstd * wv.y + bv.y;
  o.z = (x.z - mean) * rstd * wv.z + bv.z;
  o.w = (x.w - mean) * rstd * wv.w + bv.w;
  st_h4(dst + t * 4, o);
}

// ------- fp16 m16n8k16 GEMM, BK=32, 3-stage cp.async, ldmatrix frags -------
// MINBLK: min blocks/SM hint (3 on the K=512 weight GEMMs to cap regs at 85).
// 0: q = lnL@Wq^T (+b)*0.125 -> g_q(h)      1: kv = lnR@Wkv^T + b -> g_kv(h)
// 2: posp = posh@W[:1024]^T + b (cols<512 *0.125), M=511 -> g_posp(h)
// 3: T1 per (n,e): q.k^T -> A12 f32         4: T2 per (e,w): q.kr^T += A12 f32
// 5: T3 per (e,v): qr.k^T -> T3[e][w][v][n] f32
// 6: AV per (n,e): P(h)@V(h) NN -> g_vo(h)  7: out = vo@Wo^T + b + resid -> f32
template <int MODE, int BM, int BN, int MINBLK>
__global__ void __launch_bounds__(256, MINBLK)
gemm_k(const float* __restrict__ pbias, const float* __restrict__ presid,
       const int* __restrict__ pidx, float* __restrict__ pC) {
  constexpr int WGN = BN / 32;
  constexpr int WGM = 8 / WGN;
  constexpr int WM  = BM / WGM;
  constexpr int MT  = WM / 16;
  constexpr bool NN = (MODE == 6);
  constexpr int AROW = 40;                      // halves per A/B row (32 + 8 pad)
  constexpr int ASZ = BM * AROW;
  constexpr int BSZ = NN ? 32 * 72 : BN * AROW;
  extern __shared__ __half hsm[];
  __half* AsmH = hsm;
  __half* BsmH = hsm + 3 * ASZ;

  const int tid  = threadIdx.x;
  const int warp = tid >> 5;
  const int lane = tid & 31;
  const int gid  = lane >> 2;
  const int tg   = lane & 3;
  const int wm0  = (warp / WGN) * WM;
  const int wn0  = (warp % WGN) * 32;
  const int i0 = blockIdx.y * BM;
  const int j0 = blockIdx.x * BN;
  const int z  = blockIdx.z;

  const __half* A = nullptr;
  const __half* B = nullptr;
  float*  C  = nullptr;
  __half* Ch = nullptr;
  long lda = 0, ldb = 0, ldc = 0;
  int K = 0, e = 0, bb = 0;

  if constexpr (MODE == 0) { A = g_lnL; lda = 512; K = 512; B = g_wih; ldb = 512; Ch = g_q; ldc = 512; }
  else if constexpr (MODE == 1) { A = g_lnR; lda = 512; K = 512; B = g_wih + 512 * 512; ldb = 512; Ch = g_kv; ldc = 1024; }
  else if constexpr (MODE == 2) { A = g_posh; lda = 512; K = 512; B = g_wih; ldb = 512; Ch = g_posp; ldc = 1024; }
  else if constexpr (MODE == 3) { bb = z >> 3; e = z & 7;
    A = g_q + (long)bb * 512 + e * 64; lda = 65536; K = 64;
    B = g_kv + (long)bb * 1024 + e * 64; ldb = 131072;
    C = g_A12 + (long)e * 8388608 + (long)bb * 256; ldc = 32768; }
  else if constexpr (MODE == 4) { e = z >> 8; bb = z & 255;
    A = g_q + (long)bb * 65536 + e * 64; lda = 512; K = 64;
    C = g_A12 + (long)e * 8388608 + (long)bb * 32768; ldc = 256; }
  else if constexpr (MODE == 5) { e = z >> 8; bb = z & 255;
    B = g_kv + (long)bb * 131072 + e * 64; ldb = 1024; K = 64;
    C = g_T3 + (long)e * 8388608 + bb * 128; ldc = 32768; }   // [e][w][v][n]
  else if constexpr (MODE == 6) { bb = z >> 3; e = z & 7;
    A = g_P + (long)e * 8388608 + (long)bb * 256; lda = 32768; K = 256;
    B = g_kv + (long)bb * 1024 + 512 + e * 64; ldb = 131072;
    Ch = g_vo + (long)bb * 512 + e * 64; ldc = 65536; }
  else { A = g_vo; lda = 512; K = 512; B = g_woh; ldb = 512; C = pC; ldc = 512; }

  auto issue_tiles = [&](int k0, int stage) {
    __half* dstA = AsmH + stage * ASZ;
    constexpr int CA = BM * 4;   // 16B chunks in A tile (BK=32)
#pragma unroll
    for (int it = 0; it < (CA + 255) / 256; ++it) {
      int c = tid + it * 256;
      if (c < CA) {
        int i = c >> 2, kk = (c & 3) * 8;
        __half* d = dstA + i * AROW + kk;
        if constexpr (MODE == 5) {
          int gi = pidx[(i0 + i) * 256 + bb];
          cpa16(d, g_posp + (long)gi * 1024 + e * 64 + k0 + kk, true);
        } else if constexpr (MODE == 2) {
          cpa16(d, A + (long)(i0 + i) * lda + k0 + kk, i0 + i < 511);
        } else {
          cpa16(d, A + (long)(i0 + i) * lda + k0 + kk, true);
        }
      }
    }
    __half* dstB = BsmH + stage * BSZ;
    if constexpr (NN) {
      int c = tid;                            // 32 k-rows x 8 chunks = 256
      int kk = c >> 3, j = (c & 7) * 8;
      cpa16(dstB + kk * 72 + j, B + (long)(k0 + kk) * ldb + j0 + j, true);
    } else {
      constexpr int CB = BN * 4;
#pragma unroll
      for (int it = 0; it < (CB + 255) / 256; ++it) {
        int c = tid + it * 256;
        if (c < CB) {
          int j = c >> 2, kk = (c & 3) * 8;
          __half* d = dstB + j * AROW + kk;
          if constexpr (MODE == 4) {
            int gi = pidx[bb * 256 + j0 + j];
            cpa16(d, g_posp + (long)gi * 1024 + 512 + e * 64 + k0 + kk, true);
          } else {
            cpa16(d, B + (long)(j0 + j) * ldb + k0 + kk, true);
          }
        }
      }
    }
  };

  float acc[MT][4][4];
#pragma unroll
  for (int m = 0; m < MT; ++m)
#pragma unroll
    for (int n = 0; n < 4; ++n)
#pragma unroll
      for (int r = 0; r < 4; ++r) acc[m][n][r] = 0.f;

  const int NIT = K / 32;
  issue_tiles(0, 0);  cpa_commit();
  issue_tiles(32, 1); cpa_commit();

  for (int itn = 0; itn < NIT; ++itn) {
    cpa_wait1();
    __syncthreads();
    int nxt = itn + 2;
    if (nxt < NIT) issue_tiles(nxt * 32, nxt % 3);
    cpa_commit();

    const __half* ap = AsmH + (itn % 3) * ASZ;
    const __half* bp = BsmH + (itn % 3) * BSZ;
#pragma unroll
    for (int ks = 0; ks < 2; ++ks) {
      const int ko = ks * 16;
      unsigned a[MT][4], b[4][2];
      {
        int row_off = lane & 15;
        int kx = ko + ((lane >> 4) << 3);
#pragma unroll
        for (int mt = 0; mt < MT; ++mt) {
          unsigned ad = s2u(ap + (wm0 + mt * 16 + row_off) * AROW + kx);
          ldsm4(a[mt][0], a[mt][1], a[mt][2], a[mt][3], ad);
        }
      }
      if constexpr (NN) {
        int kr = ko + (lane & 15);
        int cx = (lane >> 4) << 3;
#pragma unroll
        for (int np = 0; np < 2; ++np) {
          unsigned ad = s2u(bp + kr * 72 + wn0 + np * 16 + cx);
          ldsm4t(b[np * 2][0], b[np * 2][1], b[np * 2 + 1][0], b[np * 2 + 1][1], ad);
        }
      } else {
        int row_off = ((lane >> 4) & 1) * 8 + (lane & 7);
        int kx = ko + (((lane >> 3) & 1) << 3);
#pragma unroll
        for (int np = 0; np < 2; ++np) {
          unsigned ad = s2u(bp + (wn0 + np * 16 + row_off) * AROW + kx);
          ldsm4(b[np * 2][0], b[np * 2][1], b[np * 2 + 1][0], b[np * 2 + 1][1], ad);
        }
      }
#pragma unroll
      for (int mt = 0; mt < MT; ++mt)
#pragma unroll
        for (int nt = 0; nt < 4; ++nt) mma16(acc[mt][nt], a[mt], b[nt]);
    }
  }

  // ---- epilogue ----
#pragma unroll
  for (int mt = 0; mt < MT; ++mt) {
#pragma unroll
    for (int nt = 0; nt < 4; ++nt) {
      int j = j0 + wn0 + nt * 8 + 2 * tg;
#pragma unroll
      for (int h = 0; h < 2; ++h) {
        int i = i0 + wm0 + mt * 16 + gid + h * 8;
        if constexpr (MODE == 2) { if (i >= 511) continue; }
        float v0 = acc[mt][nt][h * 2 + 0];
        float v1 = acc[mt][nt][h * 2 + 1];
        if constexpr (MODE == 0) {
          float2 bv = *reinterpret_cast<const float2*>(pbias + j);
          *reinterpret_cast<__half2*>(Ch + (long)i * ldc + j) =
              __floats2half2_rn((v0 + bv.x) * 0.125f, (v1 + bv.y) * 0.125f);
        } else if constexpr (MODE == 1) {
          float2 bv = *reinterpret_cast<const float2*>(pbias + j);
          *reinterpret_cast<__half2*>(Ch + (long)i * ldc + j) =
              __floats2half2_rn(v0 + bv.x, v1 + bv.y);
        } else if constexpr (MODE == 2) {
          float2 bv = *reinterpret_cast<const float2*>(pbias + j);
          float sc = (j < 512) ? 0.125f : 1.0f;
          *reinterpret_cast<__half2*>(Ch + (long)i * ldc + j) =
              __floats2half2_rn((v0 + bv.x) * sc, (v1 + bv.y) * sc);
        } else if constexpr (MODE == 6) {
          *reinterpret_cast<__half2*>(Ch + (long)i * ldc + j) =
              __floats2half2_rn(v0, v1);
        } else if constexpr (MODE == 4) {
          float* cp = C + (long)i * ldc + j;
          float2 o = *reinterpret_cast<const float2*>(cp);
          *reinterpret_cast<float2*>(cp) = make_float2(v0 + o.x, v1 + o.y);
        } else if constexpr (MODE == 7) {
          float2 bv = *reinterpret_cast<const float2*>(pbias + j);
          float2 rv = *reinterpret_cast<const float2*>(presid + (long)i * 512 + j);
          *reinterpret_cast<float2*>(C + (long)i * ldc + j) =
              make_float2(v0 + bv.x + rv.x, v1 + bv.y + rv.y);
        } else {  // modes 3, 5: fp32 logits
          *reinterpret_cast<float2*>(C + (long)i * ldc + j) = make_float2(v0, v1);
        }
      }
    }
  }
}

// ------- Fused T3-add + raw_attn + softmax -------
// grid (256 w, 4 n-chunks), block 1024 = 32 warps; warp wi handles n = n0+wi.
__global__ void __launch_bounds__(1024) t3_raw_sm_kernel(float* __restrict__ out2) {
  __shared__ float ts[256][33];
  const int w    = blockIdx.x;
  const int n0   = blockIdx.y * 32;
  const int tid  = threadIdx.x;
  const int wi   = tid >> 5;
  const int lane = tid & 31;
  const int n    = n0 + wi;

  float raw[8] = {0.f, 0.f, 0.f, 0.f, 0.f, 0.f, 0.f, 0.f};
  const long base_wn = (long)w * 32768 + n * 256;

#pragma unroll 1
  for (int e = 0; e < 8; ++e) {
    __syncthreads();
    const float* src = g_T3 + (long)e * 8388608 + (long)w * 32768 + n0;
#pragma unroll
    for (int it = 0; it < 8; ++it) {
      int c = tid + it * 1024;
      int vj = c >> 5, nn = c & 31;
      ts[vj][nn] = src[(long)vj * 128 + nn];
    }
    __syncthreads();

    const float* p = g_A12 + (long)e * 8388608 + base_wn;
    float x[8];
    float mx = -1e30f;
#pragma unroll
    for (int j = 0; j < 8; ++j) {
      int v = lane + j * 32;
      x[j] = p[v] + ts[v][wi];
      raw[j] += x[j];
      mx = fmaxf(mx, x[j]);
    }
#pragma unroll
    for (int o = 16; o > 0; o >>= 1) mx = fmaxf(mx, __shfl_xor_sync(0xffffffffu, mx, o));
    float s = 0.f;
#pragma unroll
    for (int j = 0; j < 8; ++j) { x[j] = __expf(x[j] - mx); s += x[j]; }
#pragma unroll
    for (int o = 16; o > 0; o >>= 1) s += __shfl_xor_sync(0xffffffffu, s, o);
    float inv = 1.0f / s;
    __half* ph = g_P + (long)e * 8388608 + base_wn;
#pragma unroll
    for (int j = 0; j < 8; ++j) ph[lane + j * 32] = __float2half(x[j] * inv);
  }

  float* rp = out2 + ((long)n * 256 + w) * 256;
#pragma unroll
  for (int j = 0; j < 8; ++j) rp[lane + j * 32] = raw[j];
}

extern "C" void kernel_launch(void* const* d_in, const int* in_sizes, int n_in,
                              void* d_out, int out_size) {
  const float* feat_left   = (const float*)d_in[0];
  const float* feat_right  = (const float*)d_in[1];
  const float* pos         = (const float*)d_in[2];
  const int*   pos_indexes = (const int*)d_in[3];
  const float* ln_w        = (const float*)d_in[4];
  const float* ln_b        = (const float*)d_in[5];
  const float* in_proj_w   = (const float*)d_in[6];
  const float* in_proj_b   = (const float*)d_in[7];
  const float* out_w       = (const float*)d_in[8];
  const float* out_b       = (const float*)d_in[9];
  float* out = (float*)d_out;

  constexpr int S128 = 3 * (128 * 40 + 128 * 40) * 2;  // 61440
  constexpr int S64  = 3 * (64 * 40 + 64 * 40) * 2;    // 30720
  constexpr int S6   = 3 * (128 * 40 + 32 * 72) * 2;   // 44544
  cudaFuncSetAttribute(gemm_k<0, 128, 128, 3>, cudaFuncAttributeMaxDynamicSharedMemorySize, S128);
  cudaFuncSetAttribute(gemm_k<1, 128, 128, 3>, cudaFuncAttributeMaxDynamicSharedMemorySize, S128);
  cudaFuncSetAttribute(gemm_k<7, 128, 128, 3>, cudaFuncAttributeMaxDynamicSharedMemorySize, S128);
  cudaFuncSetAttribute(gemm_k<2, 64, 64, 2>,   cudaFuncAttributeMaxDynamicSharedMemorySize, S64);
  cudaFuncSetAttribute(gemm_k<3, 128, 128, 2>, cudaFuncAttributeMaxDynamicSharedMemorySize, S128);
  cudaFuncSetAttribute(gemm_k<4, 128, 128, 2>, cudaFuncAttributeMaxDynamicSharedMemorySize, S128);
  cudaFuncSetAttribute(gemm_k<5, 128, 128, 2>, cudaFuncAttributeMaxDynamicSharedMemorySize, S128);
  cudaFuncSetAttribute(gemm_k<6, 128, 64, 2>,  cudaFuncAttributeMaxDynamicSharedMemorySize, S6);

  cvt_kernel<<<1280, 256>>>(in_proj_w, out_w, pos);
  ln_kernel<<<65536, 128>>>(feat_left, feat_right, ln_w, ln_b);

  gemm_k<0, 128, 128, 3><<<dim3(4, 256, 1), 256, S128>>>(
      in_proj_b, nullptr, nullptr, nullptr);
  gemm_k<1, 128, 128, 3><<<dim3(8, 256, 1), 256, S128>>>(
      in_proj_b + 512, nullptr, nullptr, nullptr);
  gemm_k<2, 64, 64, 2><<<dim3(16, 8, 1), 256, S64>>>(
      in_proj_b, nullptr, nullptr, nullptr);

  gemm_k<3, 128, 128, 2><<<dim3(2, 2, 1024), 256, S128>>>(
      nullptr, nullptr, nullptr, nullptr);
  gemm_k<4, 128, 128, 2><<<dim3(2, 1, 2048), 256, S128>>>(
      nullptr, nullptr, pos_indexes, nullptr);
  gemm_k<5, 128, 128, 2><<<dim3(1, 2, 2048), 256, S128>>>(
      nullptr, nullptr, pos_indexes, nullptr);

  t3_raw_sm_kernel<<<dim3(256, 4), 1024>>>(out + 16777216);

  gemm_k<6, 128, 64, 2><<<dim3(1, 2, 1024), 256, S6>>>(
      nullptr, nullptr, nullptr, nullptr);
  gemm_k<7, 128, 128, 3><<<dim3(4, 256, 1), 256, S128>>>(
      out_b, feat_left, nullptr, out);
}

// round 17
// speedup vs baseline: 1.2136x; 1.2136x over previous
#include <cuda_runtime.h>
#include <cuda_fp16.h>

static constexpr long kQSize = 256L * 128 * 512;        // 16,777,216
static constexpr long kAttn  = 8L * 256 * 128 * 256;    // 67,108,864

__device__ __half g_lnL[kQSize];       // LN(left)  fp16
__device__ __half g_lnR[kQSize];       // LN(right) fp16
__device__ __half g_q[kQSize];         // [w][n][c] *0.125, fp16
__device__ __half g_kv[2 * kQSize];    // [w][n][k|v] fp16
__device__ __half g_posp[511 * 1024];  // [p][q_r*0.125 | k_r] fp16
__device__ __half g_vo[kQSize];        // [w][n][c] fp16
__device__ __half g_A12[kAttn];        // logits fp16 (magnitudes O(0.3))
__device__ __half g_T3[kAttn];         // logits fp16, layout [e][w][v][n]
__device__ __half g_P[kAttn];          // probs fp16  [e][w][n][v]
__device__ __half g_wih[1536 * 512];   // in_proj_w fp16
__device__ __half g_woh[512 * 512];    // out_w fp16
__device__ __half g_posh[511 * 512];   // pos fp16

__device__ __forceinline__ float4 ld4(const float* p) {
  return *reinterpret_cast<const float4*>(p);
}
__device__ __forceinline__ void mma16(float (&d)[4], const unsigned (&a)[4],
                                      const unsigned (&b)[2]) {
  asm("mma.sync.aligned.m16n8k16.row.col.f32.f16.f16.f32 "
      "{%0,%1,%2,%3}, {%4,%5,%6,%7}, {%8,%9}, {%0,%1,%2,%3};"
      : "+f"(d[0]), "+f"(d[1]), "+f"(d[2]), "+f"(d[3])
      : "r"(a[0]), "r"(a[1]), "r"(a[2]), "r"(a[3]), "r"(b[0]), "r"(b[1]));
}
__device__ __forceinline__ unsigned s2u(const void* p) {
  return (unsigned)__cvta_generic_to_shared(p);
}
__device__ __forceinline__ void ldsm4(unsigned& r0, unsigned& r1, unsigned& r2,
                                      unsigned& r3, unsigned addr) {
  asm volatile("ldmatrix.sync.aligned.m8n8.x4.shared.b16 {%0,%1,%2,%3}, [%4];"
               : "=r"(r0), "=r"(r1), "=r"(r2), "=r"(r3) : "r"(addr));
}
__device__ __forceinline__ void ldsm4t(unsigned& r0, unsigned& r1, unsigned& r2,
                                       unsigned& r3, unsigned addr) {
  asm volatile("ldmatrix.sync.aligned.m8n8.x4.trans.shared.b16 {%0,%1,%2,%3}, [%4];"
               : "=r"(r0), "=r"(r1), "=r"(r2), "=r"(r3) : "r"(addr));
}
__device__ __forceinline__ void cpa16(void* smem_dst, const void* g, bool pred) {
  unsigned d = s2u(smem_dst);
  int sz = pred ? 16 : 0;
  asm volatile("cp.async.cg.shared.global [%0], [%1], 16, %2;"
               :: "r"(d), "l"(g), "r"(sz));
}
__device__ __forceinline__ void cpa_commit() {
  asm volatile("cp.async.commit_group;" ::: "memory");
}
__device__ __forceinline__ void cpa_wait1() {
  asm volatile("cp.async.wait_group 1;" ::: "memory");
}
__device__ __forceinline__ void st_h4(__half* p, float4 v) {
  __half2 h01 = __floats2half2_rn(v.x, v.y);
  __half2 h23 = __floats2half2_rn(v.z, v.w);
  uint2 u;
  u.x = *reinterpret_cast<unsigned*>(&h01);
  u.y = *reinterpret_cast<unsigned*>(&h23);
  *reinterpret_cast<uint2*>(p) = u;
}

// ------- Convert weights + pos to fp16 (once per launch) -------
__global__ void __launch_bounds__(256) cvt_kernel(const float* __restrict__ w_in,
                                                  const float* __restrict__ w_out,
                                                  const float* __restrict__ pos) {
  int i = blockIdx.x * 256 + threadIdx.x;  // float4 index
  if (i < 196608) {
    st_h4(g_wih + i * 4, ld4(w_in + (long)i * 4));
  } else if (i < 262144) {
    int j = i - 196608;
    st_h4(g_woh + j * 4, ld4(w_out + (long)j * 4));
  } else if (i < 327552) {
    int k = i - 262144;
    st_h4(g_posh + k * 4, ld4(pos + (long)k * 4));
  }
}

// ---------------- LayerNorm: one block per 512-float row, fp16 out ----------------
__global__ void __launch_bounds__(128) ln_kernel(const float* __restrict__ fl,
                                                 const float* __restrict__ fr,
                                                 const float* __restrict__ lw,
                                                 const float* __restrict__ lb) {
  long row = blockIdx.x;
  const float* src;
  __half* dst;
  if (row < 32768) { src = fl + row * 512;           dst = g_lnL + row * 512; }
  else             { src = fr + (row - 32768) * 512; dst = g_lnR + (row - 32768) * 512; }
  int t = threadIdx.x;
  float4 x = ld4(src + t * 4);
  float s  = x.x + x.y + x.z + x.w;
  float q2 = x.x * x.x + x.y * x.y + x.z * x.z + x.w * x.w;
#pragma unroll
  for (int o = 16; o > 0; o >>= 1) {
    s  += __shfl_xor_sync(0xffffffffu, s, o);
    q2 += __shfl_xor_sync(0xffffffffu, q2, o);
  }
  __shared__ float ss[4], sq[4];
  if ((t & 31) == 0) { ss[t >> 5] = s; sq[t >> 5] = q2; }
  __syncthreads();
  s  = ss[0] + ss[1] + ss[2] + ss[3];
  q2 = sq[0] + sq[1] + sq[2] + sq[3];
  float mean = s * (1.f / 512.f);
  float var  = q2 * (1.f / 512.f) - mean * mean;
  float rstd = rsqrtf(var + 1e-5f);
  float4 wv = ld4(lw + t * 4), bv = ld4(lb + t * 4);
  float4 o;
  o.x = (x.x - mean) * rstd * wv.x + bv.x;
  o.y = (x.y - mean) * rstd * wv.y + bv.y;
  o.z = (x.z - mean) * rstd * wv.z + bv.z;
  o.w = (x.w - mean) * rstd * wv.w + bv.w;
  st_h4(dst + t * 4, o);
}

// ------- fp16 m16n8k16 GEMM, BK=32, 3-stage cp.async, ldmatrix frags -------
// 0: q = lnL@Wq^T (+b)*0.125 -> g_q(h)      1: kv = lnR@Wkv^T + b -> g_kv(h)
// 2: posp = posh@W[:1024]^T + b (cols<512 *0.125), M=511 -> g_posp(h)
// 3: T1 per (n,e): q.k^T -> A12(h)          4: T2 per (e,w): q.kr^T += A12(h)
// 5: T3 per (e,v): qr.k^T -> T3(h) [e][w][v][n]
// 6: AV per (n,e): P(h)@V(h) NN -> g_vo(h)  7: out = vo@Wo^T + b + resid -> f32
template <int MODE, int BM, int BN>
__global__ void __launch_bounds__(256)
gemm_k(const float* __restrict__ pbias, const float* __restrict__ presid,
       const int* __restrict__ pidx, float* __restrict__ pC) {
  constexpr int WGN = BN / 32;
  constexpr int WGM = 8 / WGN;
  constexpr int WM  = BM / WGM;
  constexpr int MT  = WM / 16;
  constexpr bool NN = (MODE == 6);
  constexpr int AROW = 40;                      // halves per A/B row (32 + 8 pad)
  constexpr int ASZ = BM * AROW;
  constexpr int BSZ = NN ? 32 * 72 : BN * AROW;
  extern __shared__ __half hsm[];
  __half* AsmH = hsm;
  __half* BsmH = hsm + 3 * ASZ;

  const int tid  = threadIdx.x;
  const int warp = tid >> 5;
  const int lane = tid & 31;
  const int gid  = lane >> 2;
  const int tg   = lane & 3;
  const int wm0  = (warp / WGN) * WM;
  const int wn0  = (warp % WGN) * 32;
  const int i0 = blockIdx.y * BM;
  const int j0 = blockIdx.x * BN;
  const int z  = blockIdx.z;

  const __half* A = nullptr;
  const __half* B = nullptr;
  float*  C  = nullptr;
  __half* Ch = nullptr;
  long lda = 0, ldb = 0, ldc = 0;
  int K = 0, e = 0, bb = 0;

  if constexpr (MODE == 0) { A = g_lnL; lda = 512; K = 512; B = g_wih; ldb = 512; Ch = g_q; ldc = 512; }
  else if constexpr (MODE == 1) { A = g_lnR; lda = 512; K = 512; B = g_wih + 512 * 512; ldb = 512; Ch = g_kv; ldc = 1024; }
  else if constexpr (MODE == 2) { A = g_posh; lda = 512; K = 512; B = g_wih; ldb = 512; Ch = g_posp; ldc = 1024; }
  else if constexpr (MODE == 3) { bb = z >> 3; e = z & 7;
    A = g_q + (long)bb * 512 + e * 64; lda = 65536; K = 64;
    B = g_kv + (long)bb * 1024 + e * 64; ldb = 131072;
    Ch = g_A12 + (long)e * 8388608 + (long)bb * 256; ldc = 32768; }
  else if constexpr (MODE == 4) { e = z >> 8; bb = z & 255;
    A = g_q + (long)bb * 65536 + e * 64; lda = 512; K = 64;
    Ch = g_A12 + (long)e * 8388608 + (long)bb * 32768; ldc = 256; }
  else if constexpr (MODE == 5) { e = z >> 8; bb = z & 255;
    B = g_kv + (long)bb * 131072 + e * 64; ldb = 1024; K = 64;
    Ch = g_T3 + (long)e * 8388608 + bb * 128; ldc = 32768; }   // [e][w][v][n]
  else if constexpr (MODE == 6) { bb = z >> 3; e = z & 7;
    A = g_P + (long)e * 8388608 + (long)bb * 256; lda = 32768; K = 256;
    B = g_kv + (long)bb * 1024 + 512 + e * 64; ldb = 131072;
    Ch = g_vo + (long)bb * 512 + e * 64; ldc = 65536; }
  else { A = g_vo; lda = 512; K = 512; B = g_woh; ldb = 512; C = pC; ldc = 512; }

  auto issue_tiles = [&](int k0, int stage) {
    __half* dstA = AsmH + stage * ASZ;
    constexpr int CA = BM * 4;   // 16B chunks in A tile (BK=32)
#pragma unroll
    for (int it = 0; it < (CA + 255) / 256; ++it) {
      int c = tid + it * 256;
      if (c < CA) {
        int i = c >> 2, kk = (c & 3) * 8;
        __half* d = dstA + i * AROW + kk;
        if constexpr (MODE == 5) {
          int gi = pidx[(i0 + i) * 256 + bb];
          cpa16(d, g_posp + (long)gi * 1024 + e * 64 + k0 + kk, true);
        } else if constexpr (MODE == 2) {
          cpa16(d, A + (long)(i0 + i) * lda + k0 + kk, i0 + i < 511);
        } else {
          cpa16(d, A + (long)(i0 + i) * lda + k0 + kk, true);
        }
      }
    }
    __half* dstB = BsmH + stage * BSZ;
    if constexpr (NN) {
      int c = tid;                            // 32 k-rows x 8 chunks = 256
      int kk = c >> 3, j = (c & 7) * 8;
      cpa16(dstB + kk * 72 + j, B + (long)(k0 + kk) * ldb + j0 + j, true);
    } else {
      constexpr int CB = BN * 4;
#pragma unroll
      for (int it = 0; it < (CB + 255) / 256; ++it) {
        int c = tid + it * 256;
        if (c < CB) {
          int j = c >> 2, kk = (c & 3) * 8;
          __half* d = dstB + j * AROW + kk;
          if constexpr (MODE == 4) {
            int gi = pidx[bb * 256 + j0 + j];
            cpa16(d, g_posp + (long)gi * 1024 + 512 + e * 64 + k0 + kk, true);
          } else {
            cpa16(d, B + (long)(j0 + j) * ldb + k0 + kk, true);
          }
        }
      }
    }
  };

  float acc[MT][4][4];
#pragma unroll
  for (int m = 0; m < MT; ++m)
#pragma unroll
    for (int n = 0; n < 4; ++n)
#pragma unroll
      for (int r = 0; r < 4; ++r) acc[m][n][r] = 0.f;

  const int NIT = K / 32;
  issue_tiles(0, 0);  cpa_commit();
  issue_tiles(32, 1); cpa_commit();

  for (int itn = 0; itn < NIT; ++itn) {
    cpa_wait1();
    __syncthreads();
    int nxt = itn + 2;
    if (nxt < NIT) issue_tiles(nxt * 32, nxt % 3);
    cpa_commit();

    const __half* ap = AsmH + (itn % 3) * ASZ;
    const __half* bp = BsmH + (itn % 3) * BSZ;
#pragma unroll
    for (int ks = 0; ks < 2; ++ks) {
      const int ko = ks * 16;
      unsigned a[MT][4], b[4][2];
      {
        int row_off = lane & 15;
        int kx = ko + ((lane >> 4) << 3);
#pragma unroll
        for (int mt = 0; mt < MT; ++mt) {
          unsigned ad = s2u(ap + (wm0 + mt * 16 + row_off) * AROW + kx);
          ldsm4(a[mt][0], a[mt][1], a[mt][2], a[mt][3], ad);
        }
      }
      if constexpr (NN) {
        int kr = ko + (lane & 15);
        int cx = (lane >> 4) << 3;
#pragma unroll
        for (int np = 0; np < 2; ++np) {
          unsigned ad = s2u(bp + kr * 72 + wn0 + np * 16 + cx);
          ldsm4t(b[np * 2][0], b[np * 2][1], b[np * 2 + 1][0], b[np * 2 + 1][1], ad);
        }
      } else {
        int row_off = ((lane >> 4) & 1) * 8 + (lane & 7);
        int kx = ko + (((lane >> 3) & 1) << 3);
#pragma unroll
        for (int np = 0; np < 2; ++np) {
          unsigned ad = s2u(bp + (wn0 + np * 16 + row_off) * AROW + kx);
          ldsm4(b[np * 2][0], b[np * 2][1], b[np * 2 + 1][0], b[np * 2 + 1][1], ad);
        }
      }
#pragma unroll
      for (int mt = 0; mt < MT; ++mt)
#pragma unroll
        for (int nt = 0; nt < 4; ++nt) mma16(acc[mt][nt], a[mt], b[nt]);
    }
  }

  // ---- epilogue ----
#pragma unroll
  for (int mt = 0; mt < MT; ++mt) {
#pragma unroll
    for (int nt = 0; nt < 4; ++nt) {
      int j = j0 + wn0 + nt * 8 + 2 * tg;
#pragma unroll
      for (int h = 0; h < 2; ++h) {
        int i = i0 + wm0 + mt * 16 + gid + h * 8;
        if constexpr (MODE == 2) { if (i >= 511) continue; }
        float v0 = acc[mt][nt][h * 2 + 0];
        float v1 = acc[mt][nt][h * 2 + 1];
        if constexpr (MODE == 0) {
          float2 bv = *reinterpret_cast<const float2*>(pbias + j);
          *reinterpret_cast<__half2*>(Ch + (long)i * ldc + j) =
              __floats2half2_rn((v0 + bv.x) * 0.125f, (v1 + bv.y) * 0.125f);
        } else if constexpr (MODE == 1) {
          float2 bv = *reinterpret_cast<const float2*>(pbias + j);
          *reinterpret_cast<__half2*>(Ch + (long)i * ldc + j) =
              __floats2half2_rn(v0 + bv.x, v1 + bv.y);
        } else if constexpr (MODE == 2) {
          float2 bv = *reinterpret_cast<const float2*>(pbias + j);
          float sc = (j < 512) ? 0.125f : 1.0f;
          *reinterpret_cast<__half2*>(Ch + (long)i * ldc + j) =
              __floats2half2_rn((v0 + bv.x) * sc, (v1 + bv.y) * sc);
        } else if constexpr (MODE == 3 || MODE == 5 || MODE == 6) {
          *reinterpret_cast<__half2*>(Ch + (long)i * ldc + j) =
              __floats2half2_rn(v0, v1);
        } else if constexpr (MODE == 4) {
          __half2* hp = reinterpret_cast<__half2*>(Ch + (long)i * ldc + j);
          float2 o = __half22float2(*hp);
          *hp = __floats2half2_rn(v0 + o.x, v1 + o.y);
        } else {  // MODE 7
          float2 bv = *reinterpret_cast<const float2*>(pbias + j);
          float2 rv = *reinterpret_cast<const float2*>(presid + (long)i * 512 + j);
          *reinterpret_cast<float2*>(C + (long)i * ldc + j) =
              make_float2(v0 + bv.x + rv.x, v1 + bv.y + rv.y);
        }
      }
    }
  }
}

// ------- Fused T3-add + raw_attn + softmax (fp16 logits in, fp16 probs out) -------
// grid (256 w, 4 n-chunks), block 1024 = 32 warps; warp wi handles n = n0+wi.
__global__ void __launch_bounds__(1024) t3_raw_sm_kernel(float* __restrict__ out2) {
  __shared__ float ts[256][33];
  const int w    = blockIdx.x;
  const int n0   = blockIdx.y * 32;
  const int tid  = threadIdx.x;
  const int wi   = tid >> 5;
  const int lane = tid & 31;
  const int n    = n0 + wi;

  float raw[8] = {0.f, 0.f, 0.f, 0.f, 0.f, 0.f, 0.f, 0.f};
  const long base_wn = (long)w * 32768 + n * 256;

#pragma unroll 1
  for (int e = 0; e < 8; ++e) {
    __syncthreads();
    const __half* src = g_T3 + (long)e * 8388608 + (long)w * 32768 + n0;
#pragma unroll
    for (int it = 0; it < 8; ++it) {
      int c = tid + it * 1024;
      int vj = c >> 5, nn = c & 31;
      ts[vj][nn] = __half2float(src[(long)vj * 128 + nn]);
    }
    __syncthreads();

    const __half* p = g_A12 + (long)e * 8388608 + base_wn;
    float x[8];
    float mx = -1e30f;
#pragma unroll
    for (int j = 0; j < 8; ++j) {
      int v = lane + j * 32;
      x[j] = __half2float(p[v]) + ts[v][wi];
      raw[j] += x[j];
      mx = fmaxf(mx, x[j]);
    }
#pragma unroll
    for (int o = 16; o > 0; o >>= 1) mx = fmaxf(mx, __shfl_xor_sync(0xffffffffu, mx, o));
    float s = 0.f;
#pragma unroll
    for (int j = 0; j < 8; ++j) { x[j] = __expf(x[j] - mx); s += x[j]; }
#pragma unroll
    for (int o = 16; o > 0; o >>= 1) s += __shfl_xor_sync(0xffffffffu, s, o);
    float inv = 1.0f / s;
    __half* ph = g_P + (long)e * 8388608 + base_wn;
#pragma unroll
    for (int j = 0; j < 8; ++j) ph[lane + j * 32] = __float2half(x[j] * inv);
  }

  float* rp = out2 + ((long)n * 256 + w) * 256;
#pragma unroll
  for (int j = 0; j < 8; ++j) rp[lane + j * 32] = raw[j];
}

extern "C" void kernel_launch(void* const* d_in, const int* in_sizes, int n_in,
                              void* d_out, int out_size) {
  const float* feat_left   = (const float*)d_in[0];
  const float* feat_right  = (const float*)d_in[1];
  const float* pos         = (const float*)d_in[2];
  const int*   pos_indexes = (const int*)d_in[3];
  const float* ln_w        = (const float*)d_in[4];
  const float* ln_b        = (const float*)d_in[5];
  const float* in_proj_w   = (const float*)d_in[6];
  const float* in_proj_b   = (const float*)d_in[7];
  const float* out_w       = (const float*)d_in[8];
  const float* out_b       = (const float*)d_in[9];
  float* out = (float*)d_out;

  constexpr int S128 = 3 * (128 * 40 + 128 * 40) * 2;  // 61440
  constexpr int S64  = 3 * (64 * 40 + 64 * 40) * 2;    // 30720
  constexpr int S6   = 3 * (128 * 40 + 32 * 72) * 2;   // 44544
  cudaFuncSetAttribute(gemm_k<0, 128, 128>, cudaFuncAttributeMaxDynamicSharedMemorySize, S128);
  cudaFuncSetAttribute(gemm_k<1, 128, 128>, cudaFuncAttributeMaxDynamicSharedMemorySize, S128);
  cudaFuncSetAttribute(gemm_k<7, 128, 128>, cudaFuncAttributeMaxDynamicSharedMemorySize, S128);
  cudaFuncSetAttribute(gemm_k<2, 64, 64>,   cudaFuncAttributeMaxDynamicSharedMemorySize, S64);
  cudaFuncSetAttribute(gemm_k<3, 128, 128>, cudaFuncAttributeMaxDynamicSharedMemorySize, S128);
  cudaFuncSetAttribute(gemm_k<4, 128, 128>, cudaFuncAttributeMaxDynamicSharedMemorySize, S128);
  cudaFuncSetAttribute(gemm_k<5, 128, 128>, cudaFuncAttributeMaxDynamicSharedMemorySize, S128);
  cudaFuncSetAttribute(gemm_k<6, 128, 64>,  cudaFuncAttributeMaxDynamicSharedMemorySize, S6);

  cvt_kernel<<<1280, 256>>>(in_proj_w, out_w, pos);
  ln_kernel<<<65536, 128>>>(feat_left, feat_right, ln_w, ln_b);

  gemm_k<0, 128, 128><<<dim3(4, 256, 1), 256, S128>>>(
      in_proj_b, nullptr, nullptr, nullptr);
  gemm_k<1, 128, 128><<<dim3(8, 256, 1), 256, S128>>>(
      in_proj_b + 512, nullptr, nullptr, nullptr);
  gemm_k<2, 64, 64><<<dim3(16, 8, 1), 256, S64>>>(
      in_proj_b, nullptr, nullptr, nullptr);

  gemm_k<3, 128, 128><<<dim3(2, 2, 1024), 256, S128>>>(
      nullptr, nullptr, nullptr, nullptr);
  gemm_k<4, 128, 128><<<dim3(2, 1, 2048), 256, S128>>>(
      nullptr, nullptr, pos_indexes, nullptr);
  gemm_k<5, 128, 128><<<dim3(1, 2, 2048), 256, S128>>>(
      nullptr, nullptr, pos_indexes, nullptr);

  t3_raw_sm_kernel<<<dim3(256, 4), 1024>>>(out + 16777216);

  gemm_k<6, 128, 64><<<dim3(1, 2, 1024), 256, S6>>>(
      nullptr, nullptr, nullptr, nullptr);
  gemm_k<7, 128, 128><<<dim3(4, 256, 1), 256, S128>>>(
      out_b, feat_left, nullptr, out);
}